// round 6
// baseline (speedup 1.0000x reference)
#include <cuda_runtime.h>
#include <math.h>

// Scratch (static device globals; allocation-free)
__device__ float g_Ahat[1024 * 176];          // [i][h*44+k] = [Q*scale | w*Qg]
__device__ float g_BhatT[44 * 1024 * 4];      // [k4][j][4]  = [K | Kg] transposed
__device__ float g_cjh[1024 * 4];             // [j][h] -0.5*w*|Kg|^2
__device__ float g_Vcat[1024 * 176];          // [j][ V(128) | Vg(48) ]
__device__ float g_attn[(size_t)4 * 1024 * 1024]; // [h][i][j] UNNORMALIZED exp(l - m_chunk)
__device__ float g_mh[1024 * 64];             // [i][h*16+chunk] running max at chunk time
__device__ float g_Mf[1024 * 4];              // [i][h] final max
__device__ float g_invZ[1024 * 4];            // [i][h] 1/Z
__device__ float g_os[1024 * 128];
__device__ float g_optg[1024 * 48];
__device__ float g_opair[1024 * 256];

// ---------------------------------------------------------------------------
// kprep: layernorm + projections + frame transforms. grid=256 (4 rows), blk=256
// ---------------------------------------------------------------------------
__global__ __launch_bounds__(256) void kprep(
    const float* __restrict__ single, const float* __restrict__ T,
    const float* __restrict__ w_C,    const float* __restrict__ ln_g,
    const float* __restrict__ ln_b,
    const float* __restrict__ Wq, const float* __restrict__ Wk,
    const float* __restrict__ Wv, const float* __restrict__ Wqpt,
    const float* __restrict__ Wkpt, const float* __restrict__ Wvpt)
{
    __shared__ float zs[128 * 4];    // [d][r]
    __shared__ float proj[4][528];
    __shared__ float red[2][8];

    const int t  = threadIdx.x;
    const int i0 = blockIdx.x * 4;
    const int lane = t & 31, wid = t >> 5;

    for (int pass = 0; pass < 2; pass++) {
        const int r = pass * 2 + (t >> 7);
        const int d = t & 127;
        float x = single[(i0 + r) * 128 + d];
        float s = x, s2 = x * x;
        #pragma unroll
        for (int o = 16; o; o >>= 1) {
            s  += __shfl_xor_sync(0xffffffffu, s,  o);
            s2 += __shfl_xor_sync(0xffffffffu, s2, o);
        }
        if (lane == 0) { red[0][wid] = s; red[1][wid] = s2; }
        __syncthreads();
        const int base = (t >> 7) * 4;
        float sum  = red[0][base] + red[0][base+1] + red[0][base+2] + red[0][base+3];
        float sum2 = red[1][base] + red[1][base+1] + red[1][base+2] + red[1][base+3];
        float mu  = sum * (1.f / 128.f);
        float var = sum2 * (1.f / 128.f) - mu * mu;
        float inv = rsqrtf(var + 1e-5f);
        zs[d * 4 + r] = (x - mu) * inv * ln_g[d] + ln_b[d];
        __syncthreads();
    }

    for (int o = t; o < 528; o += 256) {
        const float* W; int col, ow;
        if      (o < 128) { W = Wq;   col = o;       ow = 128; }
        else if (o < 256) { W = Wk;   col = o - 128; ow = 128; }
        else if (o < 384) { W = Wv;   col = o - 256; ow = 128; }
        else if (o < 432) { W = Wqpt; col = o - 384; ow = 48;  }
        else if (o < 480) { W = Wkpt; col = o - 432; ow = 48;  }
        else              { W = Wvpt; col = o - 480; ow = 48;  }
        float a0 = 0.f, a1 = 0.f, a2 = 0.f, a3 = 0.f;
        #pragma unroll 8
        for (int d = 0; d < 128; d++) {
            float w = W[d * ow + col];
            float4 z = *(const float4*)&zs[d * 4];
            a0 += z.x * w; a1 += z.y * w; a2 += z.z * w; a3 += z.w * w;
        }
        proj[0][o] = a0; proj[1][o] = a1; proj[2][o] = a2; proj[3][o] = a3;
    }
    __syncthreads();

    const float scale = 0.17677669529663687f;   // 1/sqrt(32)
    for (int u = t; u < 512; u += 256) {
        int r = u >> 7, k = u & 127;
        int i = i0 + r, h = k >> 5, d = k & 31;
        int kk = h * 44 + d;
        g_Ahat[i * 176 + kk] = proj[r][k] * scale;
        g_BhatT[(kk >> 2) * 4096 + i * 4 + (kk & 3)] = proj[r][128 + k];
        g_Vcat[i * 176 + k] = proj[r][256 + k];
    }

    if (t < 16) {
        int r = t >> 2, h = t & 3;
        int i = i0 + r;
        float w = log1pf(__expf(w_C[h]));
        float R[3][3], tv[3];
        #pragma unroll
        for (int x = 0; x < 3; x++) {
            #pragma unroll
            for (int y = 0; y < 3; y++) R[x][y] = T[i * 16 + x * 4 + y];
            tv[x] = T[i * 16 + x * 4 + 3];
        }
        float kk2 = 0.f;
        #pragma unroll
        for (int p = 0; p < 4; p++) {
            float q0 = proj[r][384 + h * 12 + p * 3 + 0];
            float q1 = proj[r][384 + h * 12 + p * 3 + 1];
            float q2 = proj[r][384 + h * 12 + p * 3 + 2];
            float k0 = proj[r][432 + h * 12 + p * 3 + 0];
            float k1 = proj[r][432 + h * 12 + p * 3 + 1];
            float k2 = proj[r][432 + h * 12 + p * 3 + 2];
            float v0 = proj[r][480 + h * 12 + p * 3 + 0];
            float v1 = proj[r][480 + h * 12 + p * 3 + 1];
            float v2 = proj[r][480 + h * 12 + p * 3 + 2];
            #pragma unroll
            for (int x = 0; x < 3; x++) {
                float gq = R[x][0] * q0 + R[x][1] * q1 + R[x][2] * q2 + tv[x];
                float gk = R[x][0] * k0 + R[x][1] * k1 + R[x][2] * k2 + tv[x];
                float gv = R[x][0] * v0 + R[x][1] * v1 + R[x][2] * v2 + tv[x];
                int kki = h * 44 + 32 + p * 3 + x;
                g_Ahat[i * 176 + kki] = w * gq;
                g_BhatT[(kki >> 2) * 4096 + i * 4 + (kki & 3)] = gk;
                g_Vcat[i * 176 + 128 + h * 12 + p * 3 + x] = gv;
                kk2 += gk * gk;
            }
        }
        g_cjh[i * 4 + h] = -0.5f * w * kk2;
    }
}

// ---------------------------------------------------------------------------
// kfuse: bias + logits + ONLINE softmax + online o_pair; pair read ONCE.
// grid=512 (2 rows i per block), blk=256, static smem ~45.7KB
// ---------------------------------------------------------------------------
__global__ __launch_bounds__(256) void kfuse(const float* __restrict__ pair,
                                             const float* __restrict__ Wb)
{
    __shared__ float ps[2 * 64 * 68];       // pair chunk [r][j][c] padded
    __shared__ float bs[2 * 64 * 4];        // bias per (r,j) float4 over h
    __shared__ float part[2 * 2 * 64 * 4];  // [role][r][j] float4
    __shared__ float pp[2 * 64 * 4];        // probs chunk [r][j] float4
    __shared__ float AhatS[352];
    __shared__ float wbs[256];
    __shared__ float mred[16], zred[16];
    __shared__ float m_run[8], scale_s[8], Zs[8], invZs[8];

    const int t  = threadIdx.x;
    const int i0 = blockIdx.x * 2;

    if (t < 256) wbs[t] = Wb[t];
    for (int u = t; u < 352; u += 256) AhatS[u] = g_Ahat[i0 * 176 + u];
    if (t < 8) { m_run[t] = -1e30f; Zs[t] = 0.f; }
    float4 acc0 = make_float4(0.f, 0.f, 0.f, 0.f);
    float4 acc1 = make_float4(0.f, 0.f, 0.f, 0.f);
    __syncthreads();

    const float4* bhat4 = (const float4*)g_BhatT;
    const float4* cjh4  = (const float4*)g_cjh;
    const float4* pr4   = (const float4*)pair;

    for (int ch = 0; ch < 16; ch++) {
        const int j0 = ch * 64;

        // ---- load pair chunk (2 rows x 64 j x 64 c), coalesced ----
        #pragma unroll
        for (int q = 0; q < 8; q++) {
            int u = q * 256 + t;
            int r = u >> 10, row = (u >> 4) & 63, c4 = u & 15;
            float4 v = pr4[(size_t)(i0 + r) * 16384 + (size_t)(j0 + row) * 16 + c4];
            *(float4*)&ps[(r * 64 + row) * 68 + c4 * 4] = v;
        }
        __syncthreads();   // (a)

        // ---- L1: bias partials, 512 slots (2 per thread), q-quarter split ----
        #pragma unroll
        for (int rr = 0; rr < 2; rr++) {
            int s = rr * 256 + t;
            int r = s >> 8, j = (s >> 2) & 63, q = s & 3;
            float ax = 0.f, ay = 0.f, az = 0.f, aw = 0.f;
            #pragma unroll
            for (int c4 = 0; c4 < 4; c4++) {
                float4 p = *(const float4*)&ps[(r * 64 + j) * 68 + (q * 4 + c4) * 4];
                int cb = (q * 4 + c4) * 4;
                float4 w0 = *(const float4*)&wbs[(cb + 0) * 4];
                float4 w1 = *(const float4*)&wbs[(cb + 1) * 4];
                float4 w2 = *(const float4*)&wbs[(cb + 2) * 4];
                float4 w3 = *(const float4*)&wbs[(cb + 3) * 4];
                ax += p.x * w0.x + p.y * w1.x + p.z * w2.x + p.w * w3.x;
                ay += p.x * w0.y + p.y * w1.y + p.z * w2.y + p.w * w3.y;
                az += p.x * w0.z + p.y * w1.z + p.z * w2.z + p.w * w3.z;
                aw += p.x * w0.w + p.y * w1.w + p.z * w2.w + p.w * w3.w;
            }
            #pragma unroll
            for (int o = 1; o <= 2; o <<= 1) {
                ax += __shfl_xor_sync(0xffffffffu, ax, o);
                ay += __shfl_xor_sync(0xffffffffu, ay, o);
                az += __shfl_xor_sync(0xffffffffu, az, o);
                aw += __shfl_xor_sync(0xffffffffu, aw, o);
            }
            if (q == 0) *(float4*)&bs[(r * 64 + j) * 4] = make_float4(ax, ay, az, aw);
        }

        // ---- L2: 44-dot logit partials (t<128), Bhat read once for 2 rows ----
        if (t < 128) {
            int role = t >> 6, j = t & 63;
            int kb = role * 22;
            float s00 = 0.f, s01 = 0.f, s10 = 0.f, s11 = 0.f;
            #pragma unroll
            for (int k4 = 0; k4 < 11; k4++) {
                float4 bv = bhat4[(kb + k4) * 1024 + j0 + j];
                float4 a0 = *(const float4*)&AhatS[(kb + k4) * 4];
                float4 a1 = *(const float4*)&AhatS[176 + (kb + k4) * 4];
                s00 += bv.x * a0.x + bv.y * a0.y + bv.z * a0.z + bv.w * a0.w;
                s10 += bv.x * a1.x + bv.y * a1.y + bv.z * a1.z + bv.w * a1.w;
            }
            #pragma unroll
            for (int k4 = 11; k4 < 22; k4++) {
                float4 bv = bhat4[(kb + k4) * 1024 + j0 + j];
                float4 a0 = *(const float4*)&AhatS[(kb + k4) * 4];
                float4 a1 = *(const float4*)&AhatS[176 + (kb + k4) * 4];
                s01 += bv.x * a0.x + bv.y * a0.y + bv.z * a0.z + bv.w * a0.w;
                s11 += bv.x * a1.x + bv.y * a1.y + bv.z * a1.z + bv.w * a1.w;
            }
            float4 v0 = (role == 0) ? make_float4(s00, s01, 0.f, 0.f)
                                    : make_float4(0.f, 0.f, s00, s01);
            float4 v1 = (role == 0) ? make_float4(s10, s11, 0.f, 0.f)
                                    : make_float4(0.f, 0.f, s10, s11);
            *(float4*)&part[((role * 2 + 0) * 64 + j) * 4] = v0;
            *(float4*)&part[((role * 2 + 1) * 64 + j) * 4] = v1;
        }
        __syncthreads();   // (b)

        // ---- combine + chunk max ----
        float4 l4 = make_float4(0.f, 0.f, 0.f, 0.f);
        if (t < 128) {
            int r = t >> 6, j = t & 63;
            float4 pA = *(const float4*)&part[((0 * 2 + r) * 64 + j) * 4];
            float4 pB = *(const float4*)&part[((1 * 2 + r) * 64 + j) * 4];
            float4 bb = *(const float4*)&bs[(r * 64 + j) * 4];
            float4 cj = cjh4[j0 + j];
            l4.x = pA.x + pB.x + bb.x + cj.x;
            l4.y = pA.y + pB.y + bb.y + cj.y;
            l4.z = pA.z + pB.z + bb.z + cj.z;
            l4.w = pA.w + pB.w + bb.w + cj.w;
            float4 m4 = l4;
            #pragma unroll
            for (int o = 16; o; o >>= 1) {
                m4.x = fmaxf(m4.x, __shfl_xor_sync(0xffffffffu, m4.x, o));
                m4.y = fmaxf(m4.y, __shfl_xor_sync(0xffffffffu, m4.y, o));
                m4.z = fmaxf(m4.z, __shfl_xor_sync(0xffffffffu, m4.z, o));
                m4.w = fmaxf(m4.w, __shfl_xor_sync(0xffffffffu, m4.w, o));
            }
            if ((t & 31) == 0) *(float4*)&mred[(t >> 5) * 4] = m4;
        }
        __syncthreads();   // (c)

        if (t < 2) {
            float4 mA = *(const float4*)&mred[(2 * t) * 4];
            float4 mB = *(const float4*)&mred[(2 * t + 1) * 4];
            float4 old = *(const float4*)&m_run[t * 4];
            float4 nw;
            nw.x = fmaxf(old.x, fmaxf(mA.x, mB.x));
            nw.y = fmaxf(old.y, fmaxf(mA.y, mB.y));
            nw.z = fmaxf(old.z, fmaxf(mA.z, mB.z));
            nw.w = fmaxf(old.w, fmaxf(mA.w, mB.w));
            float4 sc;
            sc.x = __expf(old.x - nw.x); sc.y = __expf(old.y - nw.y);
            sc.z = __expf(old.z - nw.z); sc.w = __expf(old.w - nw.w);
            *(float4*)&m_run[t * 4] = nw;
            *(float4*)&scale_s[t * 4] = sc;
        }
        __syncthreads();   // (d)

        // ---- exp + Z partials + raw attn store ----
        if (t < 128) {
            int r = t >> 6, j = t & 63;
            float4 m4 = *(const float4*)&m_run[r * 4];
            float4 e4;
            e4.x = __expf(l4.x - m4.x); e4.y = __expf(l4.y - m4.y);
            e4.z = __expf(l4.z - m4.z); e4.w = __expf(l4.w - m4.w);
            *(float4*)&pp[(r * 64 + j) * 4] = e4;
            size_t ib = (size_t)(i0 + r) * 1024 + j0 + j;
            g_attn[ib]           = e4.x;
            g_attn[1048576 + ib] = e4.y;
            g_attn[2097152 + ib] = e4.z;
            g_attn[3145728 + ib] = e4.w;
            float4 z4 = e4;
            #pragma unroll
            for (int o = 16; o; o >>= 1) {
                z4.x += __shfl_xor_sync(0xffffffffu, z4.x, o);
                z4.y += __shfl_xor_sync(0xffffffffu, z4.y, o);
                z4.z += __shfl_xor_sync(0xffffffffu, z4.z, o);
                z4.w += __shfl_xor_sync(0xffffffffu, z4.w, o);
            }
            if ((t & 31) == 0) *(float4*)&zred[(t >> 5) * 4] = z4;
        }
        __syncthreads();   // (e)

        if (t < 2) {
            float4 zA = *(const float4*)&zred[(2 * t) * 4];
            float4 zB = *(const float4*)&zred[(2 * t + 1) * 4];
            float4 sc = *(const float4*)&scale_s[t * 4];
            float4 Z  = *(const float4*)&Zs[t * 4];
            Z.x = Z.x * sc.x + zA.x + zB.x;
            Z.y = Z.y * sc.y + zA.y + zB.y;
            Z.z = Z.z * sc.z + zA.z + zB.z;
            Z.w = Z.w * sc.w + zA.w + zB.w;
            *(float4*)&Zs[t * 4] = Z;
            float4 m4 = *(const float4*)&m_run[t * 4];
            int i = i0 + t;
            g_mh[i * 64 +  0 + ch] = m4.x;
            g_mh[i * 64 + 16 + ch] = m4.y;
            g_mh[i * 64 + 32 + ch] = m4.z;
            g_mh[i * 64 + 48 + ch] = m4.w;
        }

        // ---- online o_pair accumulate (all 256 threads) ----
        {
            int c = t & 63, rg = t >> 6;
            float4 s0 = *(const float4*)&scale_s[0];
            float4 s1 = *(const float4*)&scale_s[4];
            acc0.x *= s0.x; acc0.y *= s0.y; acc0.z *= s0.z; acc0.w *= s0.w;
            acc1.x *= s1.x; acc1.y *= s1.y; acc1.z *= s1.z; acc1.w *= s1.w;
            const float* p0b = ps + c;
            const float* p1b = ps + 64 * 68 + c;
            const float4* pp4 = (const float4*)pp;
            #pragma unroll 4
            for (int j = rg * 16; j < rg * 16 + 16; j++) {
                float pv0 = p0b[j * 68];
                float pv1 = p1b[j * 68];
                float4 q0 = pp4[j];
                float4 q1 = pp4[64 + j];
                acc0.x += q0.x * pv0; acc0.y += q0.y * pv0;
                acc0.z += q0.z * pv0; acc0.w += q0.w * pv0;
                acc1.x += q1.x * pv1; acc1.y += q1.y * pv1;
                acc1.z += q1.z * pv1; acc1.w += q1.w * pv1;
            }
        }
        __syncthreads();   // (f)
    }

    // ---- finalize Z ----
    if (t < 2) {
        float4 Z = *(const float4*)&Zs[t * 4];
        float4 iv = make_float4(1.f / Z.x, 1.f / Z.y, 1.f / Z.z, 1.f / Z.w);
        *(float4*)&invZs[t * 4] = iv;
        float4 m4 = *(const float4*)&m_run[t * 4];
        int i = i0 + t;
        g_Mf[i * 4 + 0] = m4.x; g_Mf[i * 4 + 1] = m4.y;
        g_Mf[i * 4 + 2] = m4.z; g_Mf[i * 4 + 3] = m4.w;
        g_invZ[i * 4 + 0] = iv.x; g_invZ[i * 4 + 1] = iv.y;
        g_invZ[i * 4 + 2] = iv.z; g_invZ[i * 4 + 3] = iv.w;
    }
    __syncthreads();

    // ---- merge o_pair partials across the 4 j-range groups (reuse ps) ----
    {
        int c = t & 63, rg = t >> 6;
        *(float4*)&ps[((rg * 2 + 0) * 64 + c) * 4] = acc0;
        *(float4*)&ps[((rg * 2 + 1) * 64 + c) * 4] = acc1;
    }
    __syncthreads();
    #pragma unroll
    for (int ss = 0; ss < 2; ss++) {
        int s = ss * 256 + t;
        int r = s >> 8, h = (s >> 6) & 3, c = s & 63;
        float v = ps[((0 + r) * 64 + c) * 4 + h] + ps[((2 + r) * 64 + c) * 4 + h]
                + ps[((4 + r) * 64 + c) * 4 + h] + ps[((6 + r) * 64 + c) * 4 + h];
        g_opair[(i0 + r) * 256 + h * 64 + c] = v * invZs[r * 4 + h];
    }
}

// ---------------------------------------------------------------------------
// kattnv: o_s = attn@V, o_pt_g = attn@Vg; applies softmax correction factor.
// grid=256 (64 i-tiles x 4 heads), blk=256
// ---------------------------------------------------------------------------
__global__ __launch_bounds__(256) void kattnv()
{
    __shared__ float As[16 * 129];
    __shared__ float Vs[128 * 45];
    __shared__ float corr_all[256];   // [rr][ch]

    const int h  = blockIdx.x & 3;
    const int i0 = (blockIdx.x >> 2) * 16;
    const int tid = threadIdx.x;
    const int r  = tid & 15;
    const int nb = tid >> 4;
    const int n2 = nb + 32;

    {
        int rr = tid >> 4, ch = tid & 15;
        int i = i0 + rr;
        corr_all[tid] = __expf(g_mh[i * 64 + h * 16 + ch] - g_Mf[i * 4 + h])
                        * g_invZ[i * 4 + h];
    }
    __syncthreads();

    float acc0 = 0.f, acc1 = 0.f, acc2 = 0.f;

    for (int j0 = 0; j0 < 1024; j0 += 128) {
        __syncthreads();
        if (tid < 128) {
            int jj = tid;
            const float4* vp = (const float4*)(g_Vcat + (size_t)(j0 + jj) * 176 + h * 32);
            #pragma unroll
            for (int q = 0; q < 8; q++) {
                float4 v = vp[q];
                Vs[jj * 45 + q * 4 + 0] = v.x; Vs[jj * 45 + q * 4 + 1] = v.y;
                Vs[jj * 45 + q * 4 + 2] = v.z; Vs[jj * 45 + q * 4 + 3] = v.w;
            }
            const float4* gp = (const float4*)(g_Vcat + (size_t)(j0 + jj) * 176 + 128 + h * 12);
            #pragma unroll
            for (int q = 0; q < 3; q++) {
                float4 v = gp[q];
                Vs[jj * 45 + 32 + q * 4 + 0] = v.x; Vs[jj * 45 + 32 + q * 4 + 1] = v.y;
                Vs[jj * 45 + 32 + q * 4 + 2] = v.z; Vs[jj * 45 + 32 + q * 4 + 3] = v.w;
            }
        } else {
            int t2 = tid - 128;
            for (int u = t2; u < 2048; u += 128) {
                int rr = u >> 7, jj = u & 127;
                float corr = corr_all[rr * 16 + ((j0 + jj) >> 6)];
                As[rr * 129 + jj] =
                    g_attn[((size_t)h * 1024 + (i0 + rr)) * 1024 + j0 + jj] * corr;
            }
        }
        __syncthreads();
        #pragma unroll 8
        for (int jj = 0; jj < 128; jj++) {
            float a = As[r * 129 + jj];
            acc0 += a * Vs[jj * 45 + nb];
            acc1 += a * Vs[jj * 45 + nb + 16];
            acc2 += a * Vs[jj * 45 + n2];
        }
    }
    int i = i0 + r;
    g_os[i * 128 + h * 32 + nb]      = acc0;
    g_os[i * 128 + h * 32 + nb + 16] = acc1;
    if (n2 < 44) g_optg[i * 48 + h * 12 + (n2 - 32)] = acc2;
}

// ---------------------------------------------------------------------------
// kfinal: rotation+norm, concat, out = single + f@Wout + b_out.
// grid=256 (4 rows/block), blk=512
// ---------------------------------------------------------------------------
__global__ __launch_bounds__(512) void kfinal(
    const float* __restrict__ single, const float* __restrict__ T,
    const float* __restrict__ Wout,   const float* __restrict__ b_out,
    float* __restrict__ out)
{
    __shared__ float fs[448 * 4];        // [k][r]
    __shared__ float part[4 * 4 * 128];  // [quarter][r][d]

    const int t  = threadIdx.x;
    const int i0 = blockIdx.x * 4;

    {
        int r = t & 3, k = t >> 2;
        fs[k * 4 + r] = g_os[(i0 + r) * 128 + k];
    }
    for (int u = t; u < 1024; u += 512) {
        int r = u & 3, k2 = u >> 2;
        fs[(128 + k2) * 4 + r] = g_opair[(i0 + r) * 256 + k2];
    }
    if (t < 64) {
        int r = t >> 4, hp = t & 15, h = hp >> 2, p = hp & 3;
        int i = i0 + r;
        float Rm[3][3], tv[3];
        #pragma unroll
        for (int y = 0; y < 3; y++) {
            #pragma unroll
            for (int x = 0; x < 3; x++) Rm[y][x] = T[i * 16 + y * 4 + x];
            tv[y] = T[i * 16 + y * 4 + 3];
        }
        float g0 = g_optg[i * 48 + h * 12 + p * 3 + 0] - tv[0];
        float g1 = g_optg[i * 48 + h * 12 + p * 3 + 1] - tv[1];
        float g2 = g_optg[i * 48 + h * 12 + p * 3 + 2] - tv[2];
        float nrm = 0.f;
        #pragma unroll
        for (int x = 0; x < 3; x++) {
            float v = Rm[0][x] * g0 + Rm[1][x] * g1 + Rm[2][x] * g2;
            fs[(384 + h * 12 + p * 3 + x) * 4 + r] = v;
            nrm += v * v;
        }
        fs[(432 + h * 4 + p) * 4 + r] = sqrtf(nrm);
    }
    __syncthreads();

    const int d = t & 127, q = t >> 7;
    float a0 = 0.f, a1 = 0.f, a2 = 0.f, a3 = 0.f;
    const int k0 = q * 112;
    #pragma unroll 8
    for (int k = k0; k < k0 + 112; k++) {
        float w = Wout[k * 128 + d];
        float4 f = *(const float4*)&fs[k * 4];
        a0 += f.x * w; a1 += f.y * w; a2 += f.z * w; a3 += f.w * w;
    }
    part[(q * 4 + 0) * 128 + d] = a0;
    part[(q * 4 + 1) * 128 + d] = a1;
    part[(q * 4 + 2) * 128 + d] = a2;
    part[(q * 4 + 3) * 128 + d] = a3;
    __syncthreads();

    {
        const int r = t >> 7, dd = t & 127;
        float s = part[(0 * 4 + r) * 128 + dd] + part[(1 * 4 + r) * 128 + dd]
                + part[(2 * 4 + r) * 128 + dd] + part[(3 * 4 + r) * 128 + dd];
        out[(i0 + r) * 128 + dd] = single[(i0 + r) * 128 + dd] + s + b_out[dd];
    }
}

// ---------------------------------------------------------------------------
extern "C" void kernel_launch(void* const* d_in, const int* in_sizes, int n_in,
                              void* d_out, int out_size)
{
    const float* single = (const float*)d_in[0];
    const float* pair   = (const float*)d_in[1];
    const float* T      = (const float*)d_in[2];
    const float* w_C    = (const float*)d_in[3];
    const float* ln_g   = (const float*)d_in[4];
    const float* ln_b   = (const float*)d_in[5];
    const float* Wq     = (const float*)d_in[6];
    const float* Wk     = (const float*)d_in[7];
    const float* Wv     = (const float*)d_in[8];
    const float* Wqpt   = (const float*)d_in[9];
    const float* Wkpt   = (const float*)d_in[10];
    const float* Wvpt   = (const float*)d_in[11];
    const float* Wb     = (const float*)d_in[12];
    const float* Wout   = (const float*)d_in[13];
    const float* b_out  = (const float*)d_in[14];
    float* out = (float*)d_out;

    kprep<<<256, 256>>>(single, T, w_C, ln_g, ln_b, Wq, Wk, Wv, Wqpt, Wkpt, Wvpt);
    kfuse<<<512, 256>>>(pair, Wb);
    kattnv<<<256, 256>>>();
    kfinal<<<256, 512>>>(single, T, Wout, b_out, out);
}

// round 7
// speedup vs baseline: 1.0511x; 1.0511x over previous
#include <cuda_runtime.h>
#include <math.h>

// Scratch (static device globals; allocation-free)
__device__ float g_Ahat[1024 * 176];          // [i][h*44+k] = [Q*scale | w*Qg]
__device__ float g_BhatT[44 * 1024 * 4];      // [k4][j][4]  = [K | Kg] transposed
__device__ float g_cjh[1024 * 4];             // [j][h] -0.5*w*|Kg|^2
__device__ float g_Vcat[1024 * 176];          // [j][ V(128) | Vg(48) ]
__device__ float g_attn[(size_t)4 * 1024 * 1024]; // [h][i][j] normalized
__device__ float g_os[1024 * 128];
__device__ float g_optg[1024 * 48];
__device__ float g_opair[1024 * 256];

// ---------------------------------------------------------------------------
// kprep: layernorm + projections + frame transforms. grid=256 (4 rows), blk=256
// ---------------------------------------------------------------------------
__global__ __launch_bounds__(256) void kprep(
    const float* __restrict__ single, const float* __restrict__ T,
    const float* __restrict__ w_C,    const float* __restrict__ ln_g,
    const float* __restrict__ ln_b,
    const float* __restrict__ Wq, const float* __restrict__ Wk,
    const float* __restrict__ Wv, const float* __restrict__ Wqpt,
    const float* __restrict__ Wkpt, const float* __restrict__ Wvpt)
{
    __shared__ float zs[128 * 4];    // [d][r]
    __shared__ float proj[4][528];
    __shared__ float red[2][8];

    const int t  = threadIdx.x;
    const int i0 = blockIdx.x * 4;
    const int lane = t & 31, wid = t >> 5;

    for (int pass = 0; pass < 2; pass++) {
        const int r = pass * 2 + (t >> 7);
        const int d = t & 127;
        float x = single[(i0 + r) * 128 + d];
        float s = x, s2 = x * x;
        #pragma unroll
        for (int o = 16; o; o >>= 1) {
            s  += __shfl_xor_sync(0xffffffffu, s,  o);
            s2 += __shfl_xor_sync(0xffffffffu, s2, o);
        }
        if (lane == 0) { red[0][wid] = s; red[1][wid] = s2; }
        __syncthreads();
        const int base = (t >> 7) * 4;
        float sum  = red[0][base] + red[0][base+1] + red[0][base+2] + red[0][base+3];
        float sum2 = red[1][base] + red[1][base+1] + red[1][base+2] + red[1][base+3];
        float mu  = sum * (1.f / 128.f);
        float var = sum2 * (1.f / 128.f) - mu * mu;
        float inv = rsqrtf(var + 1e-5f);
        zs[d * 4 + r] = (x - mu) * inv * ln_g[d] + ln_b[d];
        __syncthreads();
    }

    for (int o = t; o < 528; o += 256) {
        const float* W; int col, ow;
        if      (o < 128) { W = Wq;   col = o;       ow = 128; }
        else if (o < 256) { W = Wk;   col = o - 128; ow = 128; }
        else if (o < 384) { W = Wv;   col = o - 256; ow = 128; }
        else if (o < 432) { W = Wqpt; col = o - 384; ow = 48;  }
        else if (o < 480) { W = Wkpt; col = o - 432; ow = 48;  }
        else              { W = Wvpt; col = o - 480; ow = 48;  }
        float a0 = 0.f, a1 = 0.f, a2 = 0.f, a3 = 0.f;
        #pragma unroll 8
        for (int d = 0; d < 128; d++) {
            float w = W[d * ow + col];
            float4 z = *(const float4*)&zs[d * 4];
            a0 += z.x * w; a1 += z.y * w; a2 += z.z * w; a3 += z.w * w;
        }
        proj[0][o] = a0; proj[1][o] = a1; proj[2][o] = a2; proj[3][o] = a3;
    }
    __syncthreads();

    const float scale = 0.17677669529663687f;   // 1/sqrt(32)
    for (int u = t; u < 512; u += 256) {
        int r = u >> 7, k = u & 127;
        int i = i0 + r, h = k >> 5, d = k & 31;
        int kk = h * 44 + d;
        g_Ahat[i * 176 + kk] = proj[r][k] * scale;
        g_BhatT[(kk >> 2) * 4096 + i * 4 + (kk & 3)] = proj[r][128 + k];
        g_Vcat[i * 176 + k] = proj[r][256 + k];
    }

    if (t < 16) {
        int r = t >> 2, h = t & 3;
        int i = i0 + r;
        float w = log1pf(__expf(w_C[h]));
        float R[3][3], tv[3];
        #pragma unroll
        for (int x = 0; x < 3; x++) {
            #pragma unroll
            for (int y = 0; y < 3; y++) R[x][y] = T[i * 16 + x * 4 + y];
            tv[x] = T[i * 16 + x * 4 + 3];
        }
        float kk2 = 0.f;
        #pragma unroll
        for (int p = 0; p < 4; p++) {
            float q0 = proj[r][384 + h * 12 + p * 3 + 0];
            float q1 = proj[r][384 + h * 12 + p * 3 + 1];
            float q2 = proj[r][384 + h * 12 + p * 3 + 2];
            float k0 = proj[r][432 + h * 12 + p * 3 + 0];
            float k1 = proj[r][432 + h * 12 + p * 3 + 1];
            float k2 = proj[r][432 + h * 12 + p * 3 + 2];
            float v0 = proj[r][480 + h * 12 + p * 3 + 0];
            float v1 = proj[r][480 + h * 12 + p * 3 + 1];
            float v2 = proj[r][480 + h * 12 + p * 3 + 2];
            #pragma unroll
            for (int x = 0; x < 3; x++) {
                float gq = R[x][0] * q0 + R[x][1] * q1 + R[x][2] * q2 + tv[x];
                float gk = R[x][0] * k0 + R[x][1] * k1 + R[x][2] * k2 + tv[x];
                float gv = R[x][0] * v0 + R[x][1] * v1 + R[x][2] * v2 + tv[x];
                int kki = h * 44 + 32 + p * 3 + x;
                g_Ahat[i * 176 + kki] = w * gq;
                g_BhatT[(kki >> 2) * 4096 + i * 4 + (kki & 3)] = gk;
                g_Vcat[i * 176 + 128 + h * 12 + p * 3 + x] = gv;
                kk2 += gk * gk;
            }
        }
        g_cjh[i * 4 + h] = -0.5f * w * kk2;
    }
}

// ---------------------------------------------------------------------------
// klb: bias (pair@Wb, streamed per-block) + logits + softmax -> g_attn.
// grid=256 (4 rows/block), blk=256, dyn smem 105216 B (2 blocks/SM)
// ---------------------------------------------------------------------------
__global__ __launch_bounds__(256) void klb(const float* __restrict__ pair,
                                           const float* __restrict__ Wb)
{
    extern __shared__ float smem[];
    float* probs = smem;               // 16384  [r*4+h][1024]
    float* pc    = smem + 16384;       // 8704   [r][j][68] pair chunk
    float* Ahat  = pc + 8704;          // 704
    float* wbs   = Ahat + 704;         // 256
    float* redm  = wbs + 256;          // 128 [wid][16]
    float* reds  = redm + 128;         // 128

    const int t = threadIdx.x;
    const int i0 = blockIdx.x * 4;
    const int lane = t & 31, wid = t >> 5;

    for (int u = t; u < 704; u += 256) Ahat[u] = g_Ahat[i0 * 176 + u];
    if (t < 256) wbs[t] = Wb[t];
    __syncthreads();

    const float4* pr4 = (const float4*)pair;

    // ---- bias phase: stream pair rows once, probs[rh][j] = bias ----
    for (int ch = 0; ch < 32; ch++) {
        #pragma unroll
        for (int q = 0; q < 8; q++) {
            int u = q * 256 + t;
            int r = u >> 9, rem = u & 511, j = rem >> 4, c4 = rem & 15;
            float4 v = pr4[(size_t)(i0 + r) * 16384 + (size_t)(ch * 32 + j) * 16 + c4];
            *(float4*)&pc[(r * 32 + j) * 68 + c4 * 4] = v;
        }
        __syncthreads();
        {
            int rj = t >> 1;                  // 0..127 = (r, j)
            int r = rj >> 5, j = rj & 31;
            int half = t & 1;                 // c-range split
            float ax = 0.f, ay = 0.f, az = 0.f, aw = 0.f;
            const float* prow = &pc[(r * 32 + j) * 68 + half * 32];
            const float* wb   = &wbs[half * 128];
            #pragma unroll
            for (int c4 = 0; c4 < 8; c4++) {
                float4 p  = *(const float4*)&prow[c4 * 4];
                float4 w0 = *(const float4*)&wb[c4 * 16 + 0];
                float4 w1 = *(const float4*)&wb[c4 * 16 + 4];
                float4 w2 = *(const float4*)&wb[c4 * 16 + 8];
                float4 w3 = *(const float4*)&wb[c4 * 16 + 12];
                ax += p.x * w0.x + p.y * w1.x + p.z * w2.x + p.w * w3.x;
                ay += p.x * w0.y + p.y * w1.y + p.z * w2.y + p.w * w3.y;
                az += p.x * w0.z + p.y * w1.z + p.z * w2.z + p.w * w3.z;
                aw += p.x * w0.w + p.y * w1.w + p.z * w2.w + p.w * w3.w;
            }
            ax += __shfl_xor_sync(0xffffffffu, ax, 1);
            ay += __shfl_xor_sync(0xffffffffu, ay, 1);
            az += __shfl_xor_sync(0xffffffffu, az, 1);
            aw += __shfl_xor_sync(0xffffffffu, aw, 1);
            if (half == 0) {
                int jg = ch * 32 + j;
                probs[(r * 4 + 0) * 1024 + jg] = ax;
                probs[(r * 4 + 1) * 1024 + jg] = ay;
                probs[(r * 4 + 2) * 1024 + jg] = az;
                probs[(r * 4 + 3) * 1024 + jg] = aw;
            }
        }
        __syncthreads();
    }

    // ---- dot phase: probs += Ahat.Bhat + cj ----
    const float4* bhat4 = (const float4*)g_BhatT;
    const float4* cjh4  = (const float4*)g_cjh;

    for (int jj = 0; jj < 4; jj++) {
        int j = jj * 256 + t;
        float acc[4][4];
        #pragma unroll
        for (int r = 0; r < 4; r++)
            #pragma unroll
            for (int h = 0; h < 4; h++) acc[r][h] = 0.f;

        #pragma unroll
        for (int k4 = 0; k4 < 44; k4++) {
            const int h = k4 / 11;
            float4 bv = bhat4[k4 * 1024 + j];
            #pragma unroll
            for (int r = 0; r < 4; r++) {
                float4 av = *(const float4*)&Ahat[r * 176 + k4 * 4];
                acc[r][h] += av.x * bv.x + av.y * bv.y + av.z * bv.z + av.w * bv.w;
            }
        }
        float4 cj = cjh4[j];
        #pragma unroll
        for (int r = 0; r < 4; r++) {
            probs[(r * 4 + 0) * 1024 + j] += acc[r][0] + cj.x;
            probs[(r * 4 + 1) * 1024 + j] += acc[r][1] + cj.y;
            probs[(r * 4 + 2) * 1024 + j] += acc[r][2] + cj.z;
            probs[(r * 4 + 3) * 1024 + j] += acc[r][3] + cj.w;
        }
    }
    __syncthreads();

    // ---- softmax ----
    float mx[16];
    #pragma unroll
    for (int rh = 0; rh < 16; rh++) {
        float m = -1e30f;
        #pragma unroll
        for (int jj = 0; jj < 4; jj++) m = fmaxf(m, probs[rh * 1024 + jj * 256 + t]);
        #pragma unroll
        for (int o = 16; o; o >>= 1) m = fmaxf(m, __shfl_xor_sync(0xffffffffu, m, o));
        if (lane == 0) redm[wid * 16 + rh] = m;
    }
    __syncthreads();
    #pragma unroll
    for (int rh = 0; rh < 16; rh++) {
        float m = redm[rh];
        #pragma unroll
        for (int w = 1; w < 8; w++) m = fmaxf(m, redm[w * 16 + rh]);
        mx[rh] = m;
    }
    #pragma unroll
    for (int rh = 0; rh < 16; rh++) {
        float s = 0.f;
        #pragma unroll
        for (int jj = 0; jj < 4; jj++) {
            int j = jj * 256 + t;
            float e = __expf(probs[rh * 1024 + j] - mx[rh]);
            probs[rh * 1024 + j] = e;
            s += e;
        }
        #pragma unroll
        for (int o = 16; o; o >>= 1) s += __shfl_xor_sync(0xffffffffu, s, o);
        if (lane == 0) reds[wid * 16 + rh] = s;
    }
    __syncthreads();
    float invZ[16];
    #pragma unroll
    for (int rh = 0; rh < 16; rh++) {
        float s = 0.f;
        #pragma unroll
        for (int w = 0; w < 8; w++) s += reds[w * 16 + rh];
        invZ[rh] = 1.0f / s;
    }

    // ---- normalized write to g_attn[h][i][j] ----
    #pragma unroll
    for (int jj = 0; jj < 4; jj++) {
        int j = jj * 256 + t;
        #pragma unroll
        for (int r = 0; r < 4; r++)
            #pragma unroll
            for (int h = 0; h < 4; h++)
                g_attn[((size_t)h * 1024 + (i0 + r)) * 1024 + j] =
                    probs[(r * 4 + h) * 1024 + j] * invZ[r * 4 + h];
    }
}

// ---------------------------------------------------------------------------
// kmix2: merged tail GEMMs. blk=256, dyn smem 31296 B.
//   blocks [0, 256):    kattnv — o_s = attn@V, o_pt_g = attn@Vg (L2/FMA-bound)
//   blocks [256, 1280): kopair — o_pair = attn @ pair           (DRAM-bound)
// kattnv first so it overlaps the kopair DRAM stream from wave 1.
// ---------------------------------------------------------------------------
__global__ __launch_bounds__(256) void kmix2(const float* __restrict__ pair)
{
    extern __shared__ float sm2[];
    const int t = threadIdx.x;

    if (blockIdx.x < 256) {
        // -------- kattnv branch --------
        float* As = sm2;           // [16][129] = 2064
        float* Vs = sm2 + 2064;    // [128][45] = 5760

        const int h  = blockIdx.x & 3;
        const int i0 = (blockIdx.x >> 2) * 16;
        const int r  = t & 15;
        const int nb = t >> 4;
        const int n2 = nb + 32;

        float acc0 = 0.f, acc1 = 0.f, acc2 = 0.f;

        for (int j0 = 0; j0 < 1024; j0 += 128) {
            __syncthreads();
            if (t < 128) {
                int jj = t;
                const float4* vp = (const float4*)(g_Vcat + (size_t)(j0 + jj) * 176 + h * 32);
                #pragma unroll
                for (int q = 0; q < 8; q++) {
                    float4 v = vp[q];
                    Vs[jj * 45 + q * 4 + 0] = v.x; Vs[jj * 45 + q * 4 + 1] = v.y;
                    Vs[jj * 45 + q * 4 + 2] = v.z; Vs[jj * 45 + q * 4 + 3] = v.w;
                }
                const float4* gp = (const float4*)(g_Vcat + (size_t)(j0 + jj) * 176 + 128 + h * 12);
                #pragma unroll
                for (int q = 0; q < 3; q++) {
                    float4 v = gp[q];
                    Vs[jj * 45 + 32 + q * 4 + 0] = v.x; Vs[jj * 45 + 32 + q * 4 + 1] = v.y;
                    Vs[jj * 45 + 32 + q * 4 + 2] = v.z; Vs[jj * 45 + 32 + q * 4 + 3] = v.w;
                }
            } else {
                int t2 = t - 128;
                for (int u = t2; u < 2048; u += 128) {
                    int rr = u >> 7, jj = u & 127;
                    As[rr * 129 + jj] =
                        g_attn[((size_t)h * 1024 + (i0 + rr)) * 1024 + j0 + jj];
                }
            }
            __syncthreads();
            #pragma unroll 8
            for (int jj = 0; jj < 128; jj++) {
                float a = As[r * 129 + jj];
                acc0 += a * Vs[jj * 45 + nb];
                acc1 += a * Vs[jj * 45 + nb + 16];
                acc2 += a * Vs[jj * 45 + n2];
            }
        }
        int i = i0 + r;
        g_os[i * 128 + h * 32 + nb]      = acc0;
        g_os[i * 128 + h * 32 + nb + 16] = acc1;
        if (n2 < 44) g_optg[i * 48 + h * 12 + (n2 - 32)] = acc2;
        return;
    }

    // -------- kopair branch --------
    float* ps  = sm2;          // 4096 [h][j]
    float* red = sm2 + 4096;   // 16*64 = 1024

    const int i = blockIdx.x - 256;

    #pragma unroll
    for (int q = 0; q < 16; q++) {
        int u = q * 256 + t;
        ps[u] = g_attn[((size_t)(u >> 10) * 1024 + i) * 1024 + (u & 1023)];
    }
    __syncthreads();

    const int c = t & 63, g = t >> 6;
    const float* prow = pair + (size_t)i * 65536 + c;
    float acc[4] = {0.f, 0.f, 0.f, 0.f};

    for (int j = g; j < 1024; j += 16) {
        float p0 = prow[(j + 0)  * 64];
        float p1 = prow[(j + 4)  * 64];
        float p2 = prow[(j + 8)  * 64];
        float p3 = prow[(j + 12) * 64];
        #pragma unroll
        for (int h = 0; h < 4; h++) {
            acc[h] += ps[h * 1024 + j]      * p0
                    + ps[h * 1024 + j + 4]  * p1
                    + ps[h * 1024 + j + 8]  * p2
                    + ps[h * 1024 + j + 12] * p3;
        }
    }
    #pragma unroll
    for (int h = 0; h < 4; h++) red[(g * 4 + h) * 64 + c] = acc[h];
    __syncthreads();
    {
        const int c2 = t & 63, h2 = t >> 6;
        float s = red[(0 * 4 + h2) * 64 + c2] + red[(1 * 4 + h2) * 64 + c2]
                + red[(2 * 4 + h2) * 64 + c2] + red[(3 * 4 + h2) * 64 + c2];
        g_opair[i * 256 + h2 * 64 + c2] = s;
    }
}

// ---------------------------------------------------------------------------
// kfinal: rotation+norm, concat, out = single + f@Wout + b_out.
// grid=256 (4 rows/block), blk=512
// ---------------------------------------------------------------------------
__global__ __launch_bounds__(512) void kfinal(
    const float* __restrict__ single, const float* __restrict__ T,
    const float* __restrict__ Wout,   const float* __restrict__ b_out,
    float* __restrict__ out)
{
    __shared__ float fs[448 * 4];        // [k][r]
    __shared__ float part[4 * 4 * 128];  // [quarter][r][d]

    const int t  = threadIdx.x;
    const int i0 = blockIdx.x * 4;

    {
        int r = t & 3, k = t >> 2;
        fs[k * 4 + r] = g_os[(i0 + r) * 128 + k];
    }
    for (int u = t; u < 1024; u += 512) {
        int r = u & 3, k2 = u >> 2;
        fs[(128 + k2) * 4 + r] = g_opair[(i0 + r) * 256 + k2];
    }
    if (t < 64) {
        int r = t >> 4, hp = t & 15, h = hp >> 2, p = hp & 3;
        int i = i0 + r;
        float Rm[3][3], tv[3];
        #pragma unroll
        for (int y = 0; y < 3; y++) {
            #pragma unroll
            for (int x = 0; x < 3; x++) Rm[y][x] = T[i * 16 + y * 4 + x];
            tv[y] = T[i * 16 + y * 4 + 3];
        }
        float g0 = g_optg[i * 48 + h * 12 + p * 3 + 0] - tv[0];
        float g1 = g_optg[i * 48 + h * 12 + p * 3 + 1] - tv[1];
        float g2 = g_optg[i * 48 + h * 12 + p * 3 + 2] - tv[2];
        float nrm = 0.f;
        #pragma unroll
        for (int x = 0; x < 3; x++) {
            float v = Rm[0][x] * g0 + Rm[1][x] * g1 + Rm[2][x] * g2;
            fs[(384 + h * 12 + p * 3 + x) * 4 + r] = v;
            nrm += v * v;
        }
        fs[(432 + h * 4 + p) * 4 + r] = sqrtf(nrm);
    }
    __syncthreads();

    const int d = t & 127, q = t >> 7;
    float a0 = 0.f, a1 = 0.f, a2 = 0.f, a3 = 0.f;
    const int k0 = q * 112;
    #pragma unroll 8
    for (int k = k0; k < k0 + 112; k++) {
        float w = Wout[k * 128 + d];
        float4 f = *(const float4*)&fs[k * 4];
        a0 += f.x * w; a1 += f.y * w; a2 += f.z * w; a3 += f.w * w;
    }
    part[(q * 4 + 0) * 128 + d] = a0;
    part[(q * 4 + 1) * 128 + d] = a1;
    part[(q * 4 + 2) * 128 + d] = a2;
    part[(q * 4 + 3) * 128 + d] = a3;
    __syncthreads();

    {
        const int r = t >> 7, dd = t & 127;
        float s = part[(0 * 4 + r) * 128 + dd] + part[(1 * 4 + r) * 128 + dd]
                + part[(2 * 4 + r) * 128 + dd] + part[(3 * 4 + r) * 128 + dd];
        out[(i0 + r) * 128 + dd] = single[(i0 + r) * 128 + dd] + s + b_out[dd];
    }
}

// ---------------------------------------------------------------------------
extern "C" void kernel_launch(void* const* d_in, const int* in_sizes, int n_in,
                              void* d_out, int out_size)
{
    const float* single = (const float*)d_in[0];
    const float* pair   = (const float*)d_in[1];
    const float* T      = (const float*)d_in[2];
    const float* w_C    = (const float*)d_in[3];
    const float* ln_g   = (const float*)d_in[4];
    const float* ln_b   = (const float*)d_in[5];
    const float* Wq     = (const float*)d_in[6];
    const float* Wk     = (const float*)d_in[7];
    const float* Wv     = (const float*)d_in[8];
    const float* Wqpt   = (const float*)d_in[9];
    const float* Wkpt   = (const float*)d_in[10];
    const float* Wvpt   = (const float*)d_in[11];
    const float* Wb     = (const float*)d_in[12];
    const float* Wout   = (const float*)d_in[13];
    const float* b_out  = (const float*)d_in[14];
    float* out = (float*)d_out;

    const int klb_smem   = (16384 + 8704 + 704 + 256 + 128 + 128) * 4; // 105216 B
    const int kmix2_smem = (2064 + 5760) * 4;                          // 31296 B

    static int smem_set = 0;
    if (!smem_set) {
        cudaFuncSetAttribute(klb, cudaFuncAttributeMaxDynamicSharedMemorySize,
                             klb_smem);
        smem_set = 1;
    }

    kprep<<<256, 256>>>(single, T, w_C, ln_g, ln_b, Wq, Wk, Wv, Wqpt, Wkpt, Wvpt);
    klb<<<256, 256, klb_smem>>>(pair, Wb);
    kmix2<<<1280, 256, kmix2_smem>>>(pair);
    kfinal<<<256, 512>>>(single, T, Wout, b_out, out);
}

// round 8
// speedup vs baseline: 1.1239x; 1.0692x over previous
#include <cuda_runtime.h>
#include <math.h>

// Scratch (static device globals; allocation-free)
__device__ float g_Ahat[1024 * 176];          // [i][h*44+k] = [Q*scale | w*Qg]
__device__ float g_BhatT[44 * 1024 * 4];      // [k4][j][4]  = [K | Kg] transposed
__device__ float g_cjh[1024 * 4];             // [j][h] -0.5*w*|Kg|^2
__device__ float g_Vcat[1024 * 176];          // [j][ V(128) | Vg(48) ]
__device__ float g_logit[(size_t)1024 * 1024 * 4]; // [i][j][h] logits (16MB)
__device__ float g_attn[(size_t)4 * 1024 * 1024];  // [h][i][j] normalized (16MB)
__device__ float g_os[1024 * 128];
__device__ float g_optg[1024 * 48];
__device__ float g_opair[1024 * 256];

// ---------------------------------------------------------------------------
// kprep: layernorm + projections + frame transforms. grid=256 (4 rows), blk=256
// (identical to R4)
// ---------------------------------------------------------------------------
__global__ __launch_bounds__(256) void kprep(
    const float* __restrict__ single, const float* __restrict__ T,
    const float* __restrict__ w_C,    const float* __restrict__ ln_g,
    const float* __restrict__ ln_b,
    const float* __restrict__ Wq, const float* __restrict__ Wk,
    const float* __restrict__ Wv, const float* __restrict__ Wqpt,
    const float* __restrict__ Wkpt, const float* __restrict__ Wvpt)
{
    __shared__ float zs[128 * 4];    // [d][r]
    __shared__ float proj[4][528];
    __shared__ float red[2][8];

    const int t  = threadIdx.x;
    const int i0 = blockIdx.x * 4;
    const int lane = t & 31, wid = t >> 5;

    for (int pass = 0; pass < 2; pass++) {
        const int r = pass * 2 + (t >> 7);
        const int d = t & 127;
        float x = single[(i0 + r) * 128 + d];
        float s = x, s2 = x * x;
        #pragma unroll
        for (int o = 16; o; o >>= 1) {
            s  += __shfl_xor_sync(0xffffffffu, s,  o);
            s2 += __shfl_xor_sync(0xffffffffu, s2, o);
        }
        if (lane == 0) { red[0][wid] = s; red[1][wid] = s2; }
        __syncthreads();
        const int base = (t >> 7) * 4;
        float sum  = red[0][base] + red[0][base+1] + red[0][base+2] + red[0][base+3];
        float sum2 = red[1][base] + red[1][base+1] + red[1][base+2] + red[1][base+3];
        float mu  = sum * (1.f / 128.f);
        float var = sum2 * (1.f / 128.f) - mu * mu;
        float inv = rsqrtf(var + 1e-5f);
        zs[d * 4 + r] = (x - mu) * inv * ln_g[d] + ln_b[d];
        __syncthreads();
    }

    for (int o = t; o < 528; o += 256) {
        const float* W; int col, ow;
        if      (o < 128) { W = Wq;   col = o;       ow = 128; }
        else if (o < 256) { W = Wk;   col = o - 128; ow = 128; }
        else if (o < 384) { W = Wv;   col = o - 256; ow = 128; }
        else if (o < 432) { W = Wqpt; col = o - 384; ow = 48;  }
        else if (o < 480) { W = Wkpt; col = o - 432; ow = 48;  }
        else              { W = Wvpt; col = o - 480; ow = 48;  }
        float a0 = 0.f, a1 = 0.f, a2 = 0.f, a3 = 0.f;
        #pragma unroll 8
        for (int d = 0; d < 128; d++) {
            float w = W[d * ow + col];
            float4 z = *(const float4*)&zs[d * 4];
            a0 += z.x * w; a1 += z.y * w; a2 += z.z * w; a3 += z.w * w;
        }
        proj[0][o] = a0; proj[1][o] = a1; proj[2][o] = a2; proj[3][o] = a3;
    }
    __syncthreads();

    const float scale = 0.17677669529663687f;   // 1/sqrt(32)
    for (int u = t; u < 512; u += 256) {
        int r = u >> 7, k = u & 127;
        int i = i0 + r, h = k >> 5, d = k & 31;
        int kk = h * 44 + d;
        g_Ahat[i * 176 + kk] = proj[r][k] * scale;
        g_BhatT[(kk >> 2) * 4096 + i * 4 + (kk & 3)] = proj[r][128 + k];
        g_Vcat[i * 176 + k] = proj[r][256 + k];
    }

    if (t < 16) {
        int r = t >> 2, h = t & 3;
        int i = i0 + r;
        float w = log1pf(__expf(w_C[h]));
        float R[3][3], tv[3];
        #pragma unroll
        for (int x = 0; x < 3; x++) {
            #pragma unroll
            for (int y = 0; y < 3; y++) R[x][y] = T[i * 16 + x * 4 + y];
            tv[x] = T[i * 16 + x * 4 + 3];
        }
        float kk2 = 0.f;
        #pragma unroll
        for (int p = 0; p < 4; p++) {
            float q0 = proj[r][384 + h * 12 + p * 3 + 0];
            float q1 = proj[r][384 + h * 12 + p * 3 + 1];
            float q2 = proj[r][384 + h * 12 + p * 3 + 2];
            float k0 = proj[r][432 + h * 12 + p * 3 + 0];
            float k1 = proj[r][432 + h * 12 + p * 3 + 1];
            float k2 = proj[r][432 + h * 12 + p * 3 + 2];
            float v0 = proj[r][480 + h * 12 + p * 3 + 0];
            float v1 = proj[r][480 + h * 12 + p * 3 + 1];
            float v2 = proj[r][480 + h * 12 + p * 3 + 2];
            #pragma unroll
            for (int x = 0; x < 3; x++) {
                float gq = R[x][0] * q0 + R[x][1] * q1 + R[x][2] * q2 + tv[x];
                float gk = R[x][0] * k0 + R[x][1] * k1 + R[x][2] * k2 + tv[x];
                float gv = R[x][0] * v0 + R[x][1] * v1 + R[x][2] * v2 + tv[x];
                int kki = h * 44 + 32 + p * 3 + x;
                g_Ahat[i * 176 + kki] = w * gq;
                g_BhatT[(kki >> 2) * 4096 + i * 4 + (kki & 3)] = gk;
                g_Vcat[i * 176 + 128 + h * 12 + p * 3 + x] = gv;
                kk2 += gk * gk;
            }
        }
        g_cjh[i * 4 + h] = -0.5f * w * kk2;
    }
}

// ---------------------------------------------------------------------------
// klogit: full logits in ONE pass. grid=4096 (4i x 64j tile per block), blk=256
// One pair-tile load, one barrier, then per-thread bias + dot + cj -> g_logit.
// dyn smem 73472 B (3 blocks/SM)
// ---------------------------------------------------------------------------
__global__ __launch_bounds__(256) void klogit(const float* __restrict__ pair,
                                              const float* __restrict__ Wb)
{
    extern __shared__ float sm[];
    float* ps   = sm;              // 4*64*68 = 17408 floats
    float* Ahat = sm + 17408;      // 704
    float* wbs  = Ahat + 704;      // 256

    const int t  = threadIdx.x;
    const int i0 = (blockIdx.x >> 4) * 4;
    const int j0 = (blockIdx.x & 15) * 64;

    // load pair tile 4 rows x 64 j x 64 c (coalesced)
    const float4* pr4 = (const float4*)pair;
    #pragma unroll
    for (int q = 0; q < 16; q++) {
        int u = q * 256 + t;
        int r = u >> 10, j = (u >> 4) & 63, c4 = u & 15;
        float4 v = pr4[(size_t)(i0 + r) * 16384 + (size_t)(j0 + j) * 16 + c4];
        *(float4*)&ps[(r * 64 + j) * 68 + c4 * 4] = v;
    }
    for (int u = t; u < 704; u += 256) Ahat[u] = g_Ahat[i0 * 176 + u];
    if (t < 256) wbs[t] = Wb[t];
    __syncthreads();

    const int r = t >> 6, j = t & 63;

    // bias = pair[r][j][:] @ Wb
    float bx = 0.f, by = 0.f, bz = 0.f, bw = 0.f;
    const float* prow = &ps[(r * 64 + j) * 68];
    #pragma unroll
    for (int c4 = 0; c4 < 16; c4++) {
        float4 p  = *(const float4*)&prow[c4 * 4];
        float4 w0 = *(const float4*)&wbs[c4 * 16 + 0];
        float4 w1 = *(const float4*)&wbs[c4 * 16 + 4];
        float4 w2 = *(const float4*)&wbs[c4 * 16 + 8];
        float4 w3 = *(const float4*)&wbs[c4 * 16 + 12];
        bx += p.x * w0.x + p.y * w1.x + p.z * w2.x + p.w * w3.x;
        by += p.x * w0.y + p.y * w1.y + p.z * w2.y + p.w * w3.y;
        bz += p.x * w0.z + p.y * w1.z + p.z * w2.z + p.w * w3.z;
        bw += p.x * w0.w + p.y * w1.w + p.z * w2.w + p.w * w3.w;
    }

    // dot: Ahat[r] . Bhat[j0+j], 44 float4 groups, h = k4/11
    const float4* bhat4 = (const float4*)g_BhatT;
    float acc[4] = {0.f, 0.f, 0.f, 0.f};
    #pragma unroll
    for (int k4 = 0; k4 < 44; k4++) {
        const int h = k4 / 11;
        float4 bv = bhat4[k4 * 1024 + j0 + j];
        float4 av = *(const float4*)&Ahat[r * 176 + k4 * 4];
        acc[h] += av.x * bv.x + av.y * bv.y + av.z * bv.z + av.w * bv.w;
    }

    float4 cj = ((const float4*)g_cjh)[j0 + j];
    float4 l4;
    l4.x = bx + acc[0] + cj.x;
    l4.y = by + acc[1] + cj.y;
    l4.z = bz + acc[2] + cj.z;
    l4.w = bw + acc[3] + cj.w;
    ((float4*)g_logit)[(size_t)(i0 + r) * 1024 + j0 + j] = l4;
}

// ---------------------------------------------------------------------------
// ksm: softmax over one row i (all 4 heads) -> normalized g_attn[h][i][j].
// grid=1024, blk=256
// ---------------------------------------------------------------------------
__global__ __launch_bounds__(256) void ksm()
{
    __shared__ float redm[8 * 4];
    __shared__ float reds[8 * 4];

    const int t = threadIdx.x, i = blockIdx.x;
    const int lane = t & 31, wid = t >> 5;

    const float4* lg = ((const float4*)g_logit) + (size_t)i * 1024;
    float4 v[4];
    #pragma unroll
    for (int q = 0; q < 4; q++) v[q] = lg[q * 256 + t];

    // max per head
    float4 m = v[0];
    #pragma unroll
    for (int q = 1; q < 4; q++) {
        m.x = fmaxf(m.x, v[q].x); m.y = fmaxf(m.y, v[q].y);
        m.z = fmaxf(m.z, v[q].z); m.w = fmaxf(m.w, v[q].w);
    }
    #pragma unroll
    for (int o = 16; o; o >>= 1) {
        m.x = fmaxf(m.x, __shfl_xor_sync(0xffffffffu, m.x, o));
        m.y = fmaxf(m.y, __shfl_xor_sync(0xffffffffu, m.y, o));
        m.z = fmaxf(m.z, __shfl_xor_sync(0xffffffffu, m.z, o));
        m.w = fmaxf(m.w, __shfl_xor_sync(0xffffffffu, m.w, o));
    }
    if (lane == 0) *(float4*)&redm[wid * 4] = m;
    __syncthreads();
    float4 M = *(const float4*)&redm[0];
    #pragma unroll
    for (int w = 1; w < 8; w++) {
        float4 o = *(const float4*)&redm[w * 4];
        M.x = fmaxf(M.x, o.x); M.y = fmaxf(M.y, o.y);
        M.z = fmaxf(M.z, o.z); M.w = fmaxf(M.w, o.w);
    }

    // exp + sum
    float4 s = make_float4(0.f, 0.f, 0.f, 0.f);
    #pragma unroll
    for (int q = 0; q < 4; q++) {
        v[q].x = __expf(v[q].x - M.x); v[q].y = __expf(v[q].y - M.y);
        v[q].z = __expf(v[q].z - M.z); v[q].w = __expf(v[q].w - M.w);
        s.x += v[q].x; s.y += v[q].y; s.z += v[q].z; s.w += v[q].w;
    }
    #pragma unroll
    for (int o = 16; o; o >>= 1) {
        s.x += __shfl_xor_sync(0xffffffffu, s.x, o);
        s.y += __shfl_xor_sync(0xffffffffu, s.y, o);
        s.z += __shfl_xor_sync(0xffffffffu, s.z, o);
        s.w += __shfl_xor_sync(0xffffffffu, s.w, o);
    }
    if (lane == 0) *(float4*)&reds[wid * 4] = s;
    __syncthreads();
    float4 Z = make_float4(0.f, 0.f, 0.f, 0.f);
    #pragma unroll
    for (int w = 0; w < 8; w++) {
        float4 o = *(const float4*)&reds[w * 4];
        Z.x += o.x; Z.y += o.y; Z.z += o.z; Z.w += o.w;
    }
    float4 iz = make_float4(1.f / Z.x, 1.f / Z.y, 1.f / Z.z, 1.f / Z.w);

    // write normalized attn, [h][i][j]
    #pragma unroll
    for (int q = 0; q < 4; q++) {
        int j = q * 256 + t;
        size_t ib = (size_t)i * 1024 + j;
        g_attn[ib]           = v[q].x * iz.x;
        g_attn[1048576 + ib] = v[q].y * iz.y;
        g_attn[2097152 + ib] = v[q].z * iz.z;
        g_attn[3145728 + ib] = v[q].w * iz.w;
    }
}

// ---------------------------------------------------------------------------
// kopair: o_pair = attn @ pair. grid=1024 (one row i), blk=256 (identical to R4)
// ---------------------------------------------------------------------------
__global__ __launch_bounds__(256) void kopair(const float* __restrict__ pair)
{
    __shared__ float ps[4 * 1024];     // [h][j]
    __shared__ float red[4 * 4 * 64];  // [g][h][c]

    const int t = threadIdx.x;
    const int i = blockIdx.x;

    #pragma unroll
    for (int q = 0; q < 16; q++) {
        int u = q * 256 + t;
        ps[u] = g_attn[((size_t)(u >> 10) * 1024 + i) * 1024 + (u & 1023)];
    }
    __syncthreads();

    const int c = t & 63, g = t >> 6;
    const float* prow = pair + (size_t)i * 65536 + c;
    float acc[4] = {0.f, 0.f, 0.f, 0.f};

    for (int j = g; j < 1024; j += 16) {
        float p0 = prow[(j + 0)  * 64];
        float p1 = prow[(j + 4)  * 64];
        float p2 = prow[(j + 8)  * 64];
        float p3 = prow[(j + 12) * 64];
        #pragma unroll
        for (int h = 0; h < 4; h++) {
            acc[h] += ps[h * 1024 + j]      * p0
                    + ps[h * 1024 + j + 4]  * p1
                    + ps[h * 1024 + j + 8]  * p2
                    + ps[h * 1024 + j + 12] * p3;
        }
    }
    #pragma unroll
    for (int h = 0; h < 4; h++) red[(g * 4 + h) * 64 + c] = acc[h];
    __syncthreads();
    {
        const int c2 = t & 63, h2 = t >> 6;
        float s = red[(0 * 4 + h2) * 64 + c2] + red[(1 * 4 + h2) * 64 + c2]
                + red[(2 * 4 + h2) * 64 + c2] + red[(3 * 4 + h2) * 64 + c2];
        g_opair[i * 256 + h2 * 64 + c2] = s;
    }
}

// ---------------------------------------------------------------------------
// kattnv: o_s = attn@V, o_pt_g = attn@Vg. grid=256, blk=256 (identical to R4)
// ---------------------------------------------------------------------------
__global__ __launch_bounds__(256) void kattnv()
{
    __shared__ float As[16][129];
    __shared__ float Vs[128][45];

    const int h  = blockIdx.x & 3;
    const int i0 = (blockIdx.x >> 2) * 16;
    const int tid = threadIdx.x;
    const int r  = tid & 15;
    const int nb = tid >> 4;
    const int n2 = nb + 32;

    float acc0 = 0.f, acc1 = 0.f, acc2 = 0.f;

    for (int j0 = 0; j0 < 1024; j0 += 128) {
        __syncthreads();
        if (tid < 128) {
            int jj = tid;
            const float4* vp = (const float4*)(g_Vcat + (size_t)(j0 + jj) * 176 + h * 32);
            #pragma unroll
            for (int q = 0; q < 8; q++) {
                float4 v = vp[q];
                Vs[jj][q * 4 + 0] = v.x; Vs[jj][q * 4 + 1] = v.y;
                Vs[jj][q * 4 + 2] = v.z; Vs[jj][q * 4 + 3] = v.w;
            }
            const float4* gp = (const float4*)(g_Vcat + (size_t)(j0 + jj) * 176 + 128 + h * 12);
            #pragma unroll
            for (int q = 0; q < 3; q++) {
                float4 v = gp[q];
                Vs[jj][32 + q * 4 + 0] = v.x; Vs[jj][32 + q * 4 + 1] = v.y;
                Vs[jj][32 + q * 4 + 2] = v.z; Vs[jj][32 + q * 4 + 3] = v.w;
            }
        } else {
            int t2 = tid - 128;
            for (int u = t2; u < 2048; u += 128) {
                int rr = u >> 7, jj = u & 127;
                As[rr][jj] = g_attn[((size_t)h * 1024 + (i0 + rr)) * 1024 + j0 + jj];
            }
        }
        __syncthreads();
        #pragma unroll 8
        for (int jj = 0; jj < 128; jj++) {
            float a = As[r][jj];
            acc0 += a * Vs[jj][nb];
            acc1 += a * Vs[jj][nb + 16];
            acc2 += a * Vs[jj][n2];
        }
    }
    int i = i0 + r;
    g_os[i * 128 + h * 32 + nb]      = acc0;
    g_os[i * 128 + h * 32 + nb + 16] = acc1;
    if (n2 < 44) g_optg[i * 48 + h * 12 + (n2 - 32)] = acc2;
}

// ---------------------------------------------------------------------------
// kfinal: rotation+norm, concat, out = single + f@Wout + b_out.
// grid=256 (4 rows/block), blk=512 (identical to R4)
// ---------------------------------------------------------------------------
__global__ __launch_bounds__(512) void kfinal(
    const float* __restrict__ single, const float* __restrict__ T,
    const float* __restrict__ Wout,   const float* __restrict__ b_out,
    float* __restrict__ out)
{
    __shared__ float fs[448 * 4];        // [k][r]
    __shared__ float part[4 * 4 * 128];  // [quarter][r][d]

    const int t  = threadIdx.x;
    const int i0 = blockIdx.x * 4;

    {
        int r = t & 3, k = t >> 2;
        fs[k * 4 + r] = g_os[(i0 + r) * 128 + k];
    }
    for (int u = t; u < 1024; u += 512) {
        int r = u & 3, k2 = u >> 2;
        fs[(128 + k2) * 4 + r] = g_opair[(i0 + r) * 256 + k2];
    }
    if (t < 64) {
        int r = t >> 4, hp = t & 15, h = hp >> 2, p = hp & 3;
        int i = i0 + r;
        float Rm[3][3], tv[3];
        #pragma unroll
        for (int y = 0; y < 3; y++) {
            #pragma unroll
            for (int x = 0; x < 3; x++) Rm[y][x] = T[i * 16 + y * 4 + x];
            tv[y] = T[i * 16 + y * 4 + 3];
        }
        float g0 = g_optg[i * 48 + h * 12 + p * 3 + 0] - tv[0];
        float g1 = g_optg[i * 48 + h * 12 + p * 3 + 1] - tv[1];
        float g2 = g_optg[i * 48 + h * 12 + p * 3 + 2] - tv[2];
        float nrm = 0.f;
        #pragma unroll
        for (int x = 0; x < 3; x++) {
            float v = Rm[0][x] * g0 + Rm[1][x] * g1 + Rm[2][x] * g2;
            fs[(384 + h * 12 + p * 3 + x) * 4 + r] = v;
            nrm += v * v;
        }
        fs[(432 + h * 4 + p) * 4 + r] = sqrtf(nrm);
    }
    __syncthreads();

    const int d = t & 127, q = t >> 7;
    float a0 = 0.f, a1 = 0.f, a2 = 0.f, a3 = 0.f;
    const int k0 = q * 112;
    #pragma unroll 8
    for (int k = k0; k < k0 + 112; k++) {
        float w = Wout[k * 128 + d];
        float4 f = *(const float4*)&fs[k * 4];
        a0 += f.x * w; a1 += f.y * w; a2 += f.z * w; a3 += f.w * w;
    }
    part[(q * 4 + 0) * 128 + d] = a0;
    part[(q * 4 + 1) * 128 + d] = a1;
    part[(q * 4 + 2) * 128 + d] = a2;
    part[(q * 4 + 3) * 128 + d] = a3;
    __syncthreads();

    {
        const int r = t >> 7, dd = t & 127;
        float s = part[(0 * 4 + r) * 128 + dd] + part[(1 * 4 + r) * 128 + dd]
                + part[(2 * 4 + r) * 128 + dd] + part[(3 * 4 + r) * 128 + dd];
        out[(i0 + r) * 128 + dd] = single[(i0 + r) * 128 + dd] + s + b_out[dd];
    }
}

// ---------------------------------------------------------------------------
extern "C" void kernel_launch(void* const* d_in, const int* in_sizes, int n_in,
                              void* d_out, int out_size)
{
    const float* single = (const float*)d_in[0];
    const float* pair   = (const float*)d_in[1];
    const float* T      = (const float*)d_in[2];
    const float* w_C    = (const float*)d_in[3];
    const float* ln_g   = (const float*)d_in[4];
    const float* ln_b   = (const float*)d_in[5];
    const float* Wq     = (const float*)d_in[6];
    const float* Wk     = (const float*)d_in[7];
    const float* Wv     = (const float*)d_in[8];
    const float* Wqpt   = (const float*)d_in[9];
    const float* Wkpt   = (const float*)d_in[10];
    const float* Wvpt   = (const float*)d_in[11];
    const float* Wb     = (const float*)d_in[12];
    const float* Wout   = (const float*)d_in[13];
    const float* b_out  = (const float*)d_in[14];
    float* out = (float*)d_out;

    const int klogit_smem = (17408 + 704 + 256) * 4;   // 73472 B

    static int smem_set = 0;
    if (!smem_set) {
        cudaFuncSetAttribute(klogit, cudaFuncAttributeMaxDynamicSharedMemorySize,
                             klogit_smem);
        smem_set = 1;
    }

    kprep<<<256, 256>>>(single, T, w_C, ln_g, ln_b, Wq, Wk, Wv, Wqpt, Wkpt, Wvpt);
    klogit<<<4096, 256, klogit_smem>>>(pair, Wb);
    ksm<<<1024, 256>>>();
    kopair<<<1024, 256>>>(pair);
    kattnv<<<256, 256>>>();
    kfinal<<<256, 512>>>(single, T, Wout, b_out, out);
}

// round 9
// speedup vs baseline: 1.1520x; 1.0250x over previous
#include <cuda_runtime.h>
#include <math.h>

// Scratch (static device globals; allocation-free)
__device__ float g_Ahat[1024 * 176];          // [i][h*44+k] = [Q*scale | w*Qg]
__device__ float g_BhatT[44 * 1024 * 4];      // [k4][j][4]  = [K | Kg] transposed
__device__ float g_cjh[1024 * 4];             // [j][h] -0.5*w*|Kg|^2
__device__ float g_Vcat[1024 * 176];          // [j][ V(128) | Vg(48) ]
__device__ float g_logit[(size_t)1024 * 1024 * 4]; // [i][j][h] logits (16MB)
__device__ float g_attn[(size_t)4 * 1024 * 1024];  // [h][i][j] normalized (16MB)
__device__ float g_os[1024 * 128];
__device__ float g_optg[1024 * 48];
__device__ float g_opair[1024 * 256];

// ---------------------------------------------------------------------------
// kprep: layernorm + projections + frame transforms. grid=256 (4 rows), blk=256
// ---------------------------------------------------------------------------
__global__ __launch_bounds__(256) void kprep(
    const float* __restrict__ single, const float* __restrict__ T,
    const float* __restrict__ w_C,    const float* __restrict__ ln_g,
    const float* __restrict__ ln_b,
    const float* __restrict__ Wq, const float* __restrict__ Wk,
    const float* __restrict__ Wv, const float* __restrict__ Wqpt,
    const float* __restrict__ Wkpt, const float* __restrict__ Wvpt)
{
    __shared__ float zs[128 * 4];    // [d][r]
    __shared__ float proj[4][528];
    __shared__ float red[2][8];

    const int t  = threadIdx.x;
    const int i0 = blockIdx.x * 4;
    const int lane = t & 31, wid = t >> 5;

    for (int pass = 0; pass < 2; pass++) {
        const int r = pass * 2 + (t >> 7);
        const int d = t & 127;
        float x = single[(i0 + r) * 128 + d];
        float s = x, s2 = x * x;
        #pragma unroll
        for (int o = 16; o; o >>= 1) {
            s  += __shfl_xor_sync(0xffffffffu, s,  o);
            s2 += __shfl_xor_sync(0xffffffffu, s2, o);
        }
        if (lane == 0) { red[0][wid] = s; red[1][wid] = s2; }
        __syncthreads();
        const int base = (t >> 7) * 4;
        float sum  = red[0][base] + red[0][base+1] + red[0][base+2] + red[0][base+3];
        float sum2 = red[1][base] + red[1][base+1] + red[1][base+2] + red[1][base+3];
        float mu  = sum * (1.f / 128.f);
        float var = sum2 * (1.f / 128.f) - mu * mu;
        float inv = rsqrtf(var + 1e-5f);
        zs[d * 4 + r] = (x - mu) * inv * ln_g[d] + ln_b[d];
        __syncthreads();
    }

    for (int o = t; o < 528; o += 256) {
        const float* W; int col, ow;
        if      (o < 128) { W = Wq;   col = o;       ow = 128; }
        else if (o < 256) { W = Wk;   col = o - 128; ow = 128; }
        else if (o < 384) { W = Wv;   col = o - 256; ow = 128; }
        else if (o < 432) { W = Wqpt; col = o - 384; ow = 48;  }
        else if (o < 480) { W = Wkpt; col = o - 432; ow = 48;  }
        else              { W = Wvpt; col = o - 480; ow = 48;  }
        float a0 = 0.f, a1 = 0.f, a2 = 0.f, a3 = 0.f;
        #pragma unroll 8
        for (int d = 0; d < 128; d++) {
            float w = W[d * ow + col];
            float4 z = *(const float4*)&zs[d * 4];
            a0 += z.x * w; a1 += z.y * w; a2 += z.z * w; a3 += z.w * w;
        }
        proj[0][o] = a0; proj[1][o] = a1; proj[2][o] = a2; proj[3][o] = a3;
    }
    __syncthreads();

    const float scale = 0.17677669529663687f;   // 1/sqrt(32)
    for (int u = t; u < 512; u += 256) {
        int r = u >> 7, k = u & 127;
        int i = i0 + r, h = k >> 5, d = k & 31;
        int kk = h * 44 + d;
        g_Ahat[i * 176 + kk] = proj[r][k] * scale;
        g_BhatT[(kk >> 2) * 4096 + i * 4 + (kk & 3)] = proj[r][128 + k];
        g_Vcat[i * 176 + k] = proj[r][256 + k];
    }

    if (t < 16) {
        int r = t >> 2, h = t & 3;
        int i = i0 + r;
        float w = log1pf(__expf(w_C[h]));
        float R[3][3], tv[3];
        #pragma unroll
        for (int x = 0; x < 3; x++) {
            #pragma unroll
            for (int y = 0; y < 3; y++) R[x][y] = T[i * 16 + x * 4 + y];
            tv[x] = T[i * 16 + x * 4 + 3];
        }
        float kk2 = 0.f;
        #pragma unroll
        for (int p = 0; p < 4; p++) {
            float q0 = proj[r][384 + h * 12 + p * 3 + 0];
            float q1 = proj[r][384 + h * 12 + p * 3 + 1];
            float q2 = proj[r][384 + h * 12 + p * 3 + 2];
            float k0 = proj[r][432 + h * 12 + p * 3 + 0];
            float k1 = proj[r][432 + h * 12 + p * 3 + 1];
            float k2 = proj[r][432 + h * 12 + p * 3 + 2];
            float v0 = proj[r][480 + h * 12 + p * 3 + 0];
            float v1 = proj[r][480 + h * 12 + p * 3 + 1];
            float v2 = proj[r][480 + h * 12 + p * 3 + 2];
            #pragma unroll
            for (int x = 0; x < 3; x++) {
                float gq = R[x][0] * q0 + R[x][1] * q1 + R[x][2] * q2 + tv[x];
                float gk = R[x][0] * k0 + R[x][1] * k1 + R[x][2] * k2 + tv[x];
                float gv = R[x][0] * v0 + R[x][1] * v1 + R[x][2] * v2 + tv[x];
                int kki = h * 44 + 32 + p * 3 + x;
                g_Ahat[i * 176 + kki] = w * gq;
                g_BhatT[(kki >> 2) * 4096 + i * 4 + (kki & 3)] = gk;
                g_Vcat[i * 176 + 128 + h * 12 + p * 3 + x] = gv;
                kk2 += gk * gk;
            }
        }
        g_cjh[i * 4 + h] = -0.5f * w * kk2;
    }
}

// ---------------------------------------------------------------------------
// klogit: full logits in ONE pass. grid=4096 (4i x 64j tile per block), blk=256
// dyn smem 73472 B (3 blocks/SM)
// ---------------------------------------------------------------------------
__global__ __launch_bounds__(256) void klogit(const float* __restrict__ pair,
                                              const float* __restrict__ Wb)
{
    extern __shared__ float sm[];
    float* ps   = sm;              // 4*64*68 = 17408 floats
    float* Ahat = sm + 17408;      // 704
    float* wbs  = Ahat + 704;      // 256

    const int t  = threadIdx.x;
    const int i0 = (blockIdx.x >> 4) * 4;
    const int j0 = (blockIdx.x & 15) * 64;

    const float4* pr4 = (const float4*)pair;
    #pragma unroll
    for (int q = 0; q < 16; q++) {
        int u = q * 256 + t;
        int r = u >> 10, j = (u >> 4) & 63, c4 = u & 15;
        float4 v = pr4[(size_t)(i0 + r) * 16384 + (size_t)(j0 + j) * 16 + c4];
        *(float4*)&ps[(r * 64 + j) * 68 + c4 * 4] = v;
    }
    for (int u = t; u < 704; u += 256) Ahat[u] = g_Ahat[i0 * 176 + u];
    if (t < 256) wbs[t] = Wb[t];
    __syncthreads();

    const int r = t >> 6, j = t & 63;

    float bx = 0.f, by = 0.f, bz = 0.f, bw = 0.f;
    const float* prow = &ps[(r * 64 + j) * 68];
    #pragma unroll
    for (int c4 = 0; c4 < 16; c4++) {
        float4 p  = *(const float4*)&prow[c4 * 4];
        float4 w0 = *(const float4*)&wbs[c4 * 16 + 0];
        float4 w1 = *(const float4*)&wbs[c4 * 16 + 4];
        float4 w2 = *(const float4*)&wbs[c4 * 16 + 8];
        float4 w3 = *(const float4*)&wbs[c4 * 16 + 12];
        bx += p.x * w0.x + p.y * w1.x + p.z * w2.x + p.w * w3.x;
        by += p.x * w0.y + p.y * w1.y + p.z * w2.y + p.w * w3.y;
        bz += p.x * w0.z + p.y * w1.z + p.z * w2.z + p.w * w3.z;
        bw += p.x * w0.w + p.y * w1.w + p.z * w2.w + p.w * w3.w;
    }

    const float4* bhat4 = (const float4*)g_BhatT;
    float acc[4] = {0.f, 0.f, 0.f, 0.f};
    #pragma unroll
    for (int k4 = 0; k4 < 44; k4++) {
        const int h = k4 / 11;
        float4 bv = bhat4[k4 * 1024 + j0 + j];
        float4 av = *(const float4*)&Ahat[r * 176 + k4 * 4];
        acc[h] += av.x * bv.x + av.y * bv.y + av.z * bv.z + av.w * bv.w;
    }

    float4 cj = ((const float4*)g_cjh)[j0 + j];
    float4 l4;
    l4.x = bx + acc[0] + cj.x;
    l4.y = by + acc[1] + cj.y;
    l4.z = bz + acc[2] + cj.z;
    l4.w = bw + acc[3] + cj.w;
    ((float4*)g_logit)[(size_t)(i0 + r) * 1024 + j0 + j] = l4;
}

// ---------------------------------------------------------------------------
// kopairsm: softmax (from g_logit) + write g_attn + o_pair = attn @ pair.
// grid=1024 (one row i), blk=256, static smem ~33KB
// ---------------------------------------------------------------------------
__global__ __launch_bounds__(256) void kopairsm(const float* __restrict__ pair)
{
    __shared__ float ps[4 * 1024];      // [h][j] normalized probs
    __shared__ float red4[16 * 4 * 16 * 4];  // [g][h][c4][4]
    __shared__ float redm[8 * 4];
    __shared__ float reds[8 * 4];

    const int t = threadIdx.x, i = blockIdx.x;
    const int lane = t & 31, wid = t >> 5;

    // ---- softmax over the logit row ----
    const float4* lg = ((const float4*)g_logit) + (size_t)i * 1024;
    float4 v[4];
    #pragma unroll
    for (int q = 0; q < 4; q++) v[q] = lg[q * 256 + t];

    float4 m = v[0];
    #pragma unroll
    for (int q = 1; q < 4; q++) {
        m.x = fmaxf(m.x, v[q].x); m.y = fmaxf(m.y, v[q].y);
        m.z = fmaxf(m.z, v[q].z); m.w = fmaxf(m.w, v[q].w);
    }
    #pragma unroll
    for (int o = 16; o; o >>= 1) {
        m.x = fmaxf(m.x, __shfl_xor_sync(0xffffffffu, m.x, o));
        m.y = fmaxf(m.y, __shfl_xor_sync(0xffffffffu, m.y, o));
        m.z = fmaxf(m.z, __shfl_xor_sync(0xffffffffu, m.z, o));
        m.w = fmaxf(m.w, __shfl_xor_sync(0xffffffffu, m.w, o));
    }
    if (lane == 0) *(float4*)&redm[wid * 4] = m;
    __syncthreads();
    float4 M = *(const float4*)&redm[0];
    #pragma unroll
    for (int w = 1; w < 8; w++) {
        float4 o = *(const float4*)&redm[w * 4];
        M.x = fmaxf(M.x, o.x); M.y = fmaxf(M.y, o.y);
        M.z = fmaxf(M.z, o.z); M.w = fmaxf(M.w, o.w);
    }

    float4 s = make_float4(0.f, 0.f, 0.f, 0.f);
    #pragma unroll
    for (int q = 0; q < 4; q++) {
        v[q].x = __expf(v[q].x - M.x); v[q].y = __expf(v[q].y - M.y);
        v[q].z = __expf(v[q].z - M.z); v[q].w = __expf(v[q].w - M.w);
        s.x += v[q].x; s.y += v[q].y; s.z += v[q].z; s.w += v[q].w;
    }
    #pragma unroll
    for (int o = 16; o; o >>= 1) {
        s.x += __shfl_xor_sync(0xffffffffu, s.x, o);
        s.y += __shfl_xor_sync(0xffffffffu, s.y, o);
        s.z += __shfl_xor_sync(0xffffffffu, s.z, o);
        s.w += __shfl_xor_sync(0xffffffffu, s.w, o);
    }
    if (lane == 0) *(float4*)&reds[wid * 4] = s;
    __syncthreads();
    float4 Z = make_float4(0.f, 0.f, 0.f, 0.f);
    #pragma unroll
    for (int w = 0; w < 8; w++) {
        float4 o = *(const float4*)&reds[w * 4];
        Z.x += o.x; Z.y += o.y; Z.z += o.z; Z.w += o.w;
    }
    float4 iz = make_float4(1.f / Z.x, 1.f / Z.y, 1.f / Z.z, 1.f / Z.w);

    // normalized probs -> smem + g_attn (for kattnv)
    #pragma unroll
    for (int q = 0; q < 4; q++) {
        int j = q * 256 + t;
        float px = v[q].x * iz.x, py = v[q].y * iz.y;
        float pz = v[q].z * iz.z, pw = v[q].w * iz.w;
        ps[j]        = px;  ps[1024 + j] = py;
        ps[2048 + j] = pz;  ps[3072 + j] = pw;
        size_t ib = (size_t)i * 1024 + j;
        g_attn[ib]           = px;
        g_attn[1048576 + ib] = py;
        g_attn[2097152 + ib] = pz;
        g_attn[3145728 + ib] = pw;
    }
    __syncthreads();

    // ---- pair stream, float4 per thread ----
    const int c4 = t & 15, g = t >> 4;   // c4: 4-channel group, g: j-group
    const float4* prow4 = (const float4*)(pair + (size_t)i * 65536);
    float4 a0 = make_float4(0,0,0,0), a1 = a0, a2 = a0, a3 = a0;

    #pragma unroll 4
    for (int j = g; j < 1024; j += 16) {
        float4 p = prow4[j * 16 + c4];
        float w0 = ps[j], w1 = ps[1024 + j], w2 = ps[2048 + j], w3 = ps[3072 + j];
        a0.x += p.x * w0; a0.y += p.y * w0; a0.z += p.z * w0; a0.w += p.w * w0;
        a1.x += p.x * w1; a1.y += p.y * w1; a1.z += p.z * w1; a1.w += p.w * w1;
        a2.x += p.x * w2; a2.y += p.y * w2; a2.z += p.z * w2; a2.w += p.w * w2;
        a3.x += p.x * w3; a3.y += p.y * w3; a3.z += p.z * w3; a3.w += p.w * w3;
    }
    *(float4*)&red4[((g * 4 + 0) * 16 + c4) * 4] = a0;
    *(float4*)&red4[((g * 4 + 1) * 16 + c4) * 4] = a1;
    *(float4*)&red4[((g * 4 + 2) * 16 + c4) * 4] = a2;
    *(float4*)&red4[((g * 4 + 3) * 16 + c4) * 4] = a3;
    __syncthreads();

    if (t < 64) {
        const int h2 = t >> 4, c2 = t & 15;
        float4 sum = make_float4(0,0,0,0);
        #pragma unroll
        for (int g2 = 0; g2 < 16; g2++) {
            float4 p = *(const float4*)&red4[((g2 * 4 + h2) * 16 + c2) * 4];
            sum.x += p.x; sum.y += p.y; sum.z += p.z; sum.w += p.w;
        }
        *(float4*)&g_opair[i * 256 + h2 * 64 + c2 * 4] = sum;
    }
}

// ---------------------------------------------------------------------------
// kattnv: o_s = attn@V, o_pt_g = attn@Vg. grid=256, blk=256.
// float4 register tiling: thread = (row r, 4-wide n group).
// ---------------------------------------------------------------------------
__global__ __launch_bounds__(256) void kattnv()
{
    __shared__ float As[16 * 132];   // [r][jj], rows 16B-aligned (132*4=528)
    __shared__ float Vs[128 * 48];   // [jj][n], rows 16B-aligned (48*4=192)

    const int h  = blockIdx.x & 3;
    const int i0 = (blockIdx.x >> 2) * 16;
    const int t  = threadIdx.x;
    const int r  = t & 15;
    const int ng = t >> 4;          // 0..15; compute if ng < 11 (44 = 11*4)

    float4 acc = make_float4(0,0,0,0);

    for (int j0 = 0; j0 < 1024; j0 += 128) {
        __syncthreads();
        if (t < 128) {
            int jj = t;
            const float4* vp = (const float4*)(g_Vcat + (size_t)(j0 + jj) * 176 + h * 32);
            #pragma unroll
            for (int q = 0; q < 8; q++)
                *(float4*)&Vs[jj * 48 + q * 4] = vp[q];
            const float4* gp = (const float4*)(g_Vcat + (size_t)(j0 + jj) * 176 + 128 + h * 12);
            #pragma unroll
            for (int q = 0; q < 3; q++)
                *(float4*)&Vs[jj * 48 + 32 + q * 4] = gp[q];
        } else {
            int t2 = t - 128;
            #pragma unroll
            for (int q = 0; q < 16; q++) {
                int u = q * 128 + t2;
                int rr = u >> 7, jj = u & 127;
                As[rr * 132 + jj] = g_attn[((size_t)h * 1024 + (i0 + rr)) * 1024 + j0 + jj];
            }
        }
        __syncthreads();
        if (ng < 11) {
            #pragma unroll 8
            for (int jq = 0; jq < 32; jq++) {
                float4 a4 = *(const float4*)&As[r * 132 + jq * 4];
                float4 v0 = *(const float4*)&Vs[(jq * 4 + 0) * 48 + ng * 4];
                float4 v1 = *(const float4*)&Vs[(jq * 4 + 1) * 48 + ng * 4];
                float4 v2 = *(const float4*)&Vs[(jq * 4 + 2) * 48 + ng * 4];
                float4 v3 = *(const float4*)&Vs[(jq * 4 + 3) * 48 + ng * 4];
                acc.x += a4.x * v0.x + a4.y * v1.x + a4.z * v2.x + a4.w * v3.x;
                acc.y += a4.x * v0.y + a4.y * v1.y + a4.z * v2.y + a4.w * v3.y;
                acc.z += a4.x * v0.z + a4.y * v1.z + a4.z * v2.z + a4.w * v3.z;
                acc.w += a4.x * v0.w + a4.y * v1.w + a4.z * v2.w + a4.w * v3.w;
            }
        }
    }
    if (ng < 8) {
        *(float4*)&g_os[(i0 + r) * 128 + h * 32 + ng * 4] = acc;
    } else if (ng < 11) {
        *(float4*)&g_optg[(i0 + r) * 48 + h * 12 + (ng - 8) * 4] = acc;
    }
}

// ---------------------------------------------------------------------------
// kfinal: rotation+norm, concat, out = single + f@Wout + b_out.
// grid=256 (4 rows/block), blk=512
// ---------------------------------------------------------------------------
__global__ __launch_bounds__(512) void kfinal(
    const float* __restrict__ single, const float* __restrict__ T,
    const float* __restrict__ Wout,   const float* __restrict__ b_out,
    float* __restrict__ out)
{
    __shared__ float fs[448 * 4];        // [k][r]
    __shared__ float part[4 * 4 * 128];  // [quarter][r][d]

    const int t  = threadIdx.x;
    const int i0 = blockIdx.x * 4;

    {
        int r = t & 3, k = t >> 2;
        fs[k * 4 + r] = g_os[(i0 + r) * 128 + k];
    }
    for (int u = t; u < 1024; u += 512) {
        int r = u & 3, k2 = u >> 2;
        fs[(128 + k2) * 4 + r] = g_opair[(i0 + r) * 256 + k2];
    }
    if (t < 64) {
        int r = t >> 4, hp = t & 15, h = hp >> 2, p = hp & 3;
        int i = i0 + r;
        float Rm[3][3], tv[3];
        #pragma unroll
        for (int y = 0; y < 3; y++) {
            #pragma unroll
            for (int x = 0; x < 3; x++) Rm[y][x] = T[i * 16 + y * 4 + x];
            tv[y] = T[i * 16 + y * 4 + 3];
        }
        float g0 = g_optg[i * 48 + h * 12 + p * 3 + 0] - tv[0];
        float g1 = g_optg[i * 48 + h * 12 + p * 3 + 1] - tv[1];
        float g2 = g_optg[i * 48 + h * 12 + p * 3 + 2] - tv[2];
        float nrm = 0.f;
        #pragma unroll
        for (int x = 0; x < 3; x++) {
            float v = Rm[0][x] * g0 + Rm[1][x] * g1 + Rm[2][x] * g2;
            fs[(384 + h * 12 + p * 3 + x) * 4 + r] = v;
            nrm += v * v;
        }
        fs[(432 + h * 4 + p) * 4 + r] = sqrtf(nrm);
    }
    __syncthreads();

    const int d = t & 127, q = t >> 7;
    float a0 = 0.f, a1 = 0.f, a2 = 0.f, a3 = 0.f;
    const int k0 = q * 112;
    #pragma unroll 8
    for (int k = k0; k < k0 + 112; k++) {
        float w = Wout[k * 128 + d];
        float4 f = *(const float4*)&fs[k * 4];
        a0 += f.x * w; a1 += f.y * w; a2 += f.z * w; a3 += f.w * w;
    }
    part[(q * 4 + 0) * 128 + d] = a0;
    part[(q * 4 + 1) * 128 + d] = a1;
    part[(q * 4 + 2) * 128 + d] = a2;
    part[(q * 4 + 3) * 128 + d] = a3;
    __syncthreads();

    {
        const int r = t >> 7, dd = t & 127;
        float s = part[(0 * 4 + r) * 128 + dd] + part[(1 * 4 + r) * 128 + dd]
                + part[(2 * 4 + r) * 128 + dd] + part[(3 * 4 + r) * 128 + dd];
        out[(i0 + r) * 128 + dd] = single[(i0 + r) * 128 + dd] + s + b_out[dd];
    }
}

// ---------------------------------------------------------------------------
extern "C" void kernel_launch(void* const* d_in, const int* in_sizes, int n_in,
                              void* d_out, int out_size)
{
    const float* single = (const float*)d_in[0];
    const float* pair   = (const float*)d_in[1];
    const float* T      = (const float*)d_in[2];
    const float* w_C    = (const float*)d_in[3];
    const float* ln_g   = (const float*)d_in[4];
    const float* ln_b   = (const float*)d_in[5];
    const float* Wq     = (const float*)d_in[6];
    const float* Wk     = (const float*)d_in[7];
    const float* Wv     = (const float*)d_in[8];
    const float* Wqpt   = (const float*)d_in[9];
    const float* Wkpt   = (const float*)d_in[10];
    const float* Wvpt   = (const float*)d_in[11];
    const float* Wb     = (const float*)d_in[12];
    const float* Wout   = (const float*)d_in[13];
    const float* b_out  = (const float*)d_in[14];
    float* out = (float*)d_out;

    const int klogit_smem = (17408 + 704 + 256) * 4;   // 73472 B

    static int smem_set = 0;
    if (!smem_set) {
        cudaFuncSetAttribute(klogit, cudaFuncAttributeMaxDynamicSharedMemorySize,
                             klogit_smem);
        smem_set = 1;
    }

    kprep<<<256, 256>>>(single, T, w_C, ln_g, ln_b, Wq, Wk, Wv, Wqpt, Wkpt, Wvpt);
    klogit<<<4096, 256, klogit_smem>>>(pair, Wb);
    kopairsm<<<1024, 256>>>(pair);
    kattnv<<<256, 256>>>();
    kfinal<<<256, 512>>>(single, T, Wout, b_out, out);
}